// round 1
// baseline (speedup 1.0000x reference)
#include <cuda_runtime.h>
#include <math.h>

#define BB 4
#define SS 2048
#define EE 1024
#define HH 16
#define DD 64
#define MM (BB*SS)

// Scratch for projected q, k, v: [B*S, E] row-major (col = h*64 + d)
__device__ float g_q[MM * EE];
__device__ float g_k[MM * EE];
__device__ float g_v[MM * EE];

// ---------------------------------------------------------------------------
// Projection SGEMM: C[m,n] = sum_k A[m,k] * W[n,k] + bias[n]
// A: [M=8192, K=1024], W: [N=1024, K=1024] (torch Linear weight), C: [M, N]
// 128x128 block tile, BK=8, 8x8 microtile, 256 threads.
// ---------------------------------------------------------------------------
__global__ __launch_bounds__(256, 2)
void proj_gemm(const float* __restrict__ A, const float* __restrict__ W,
               const float* __restrict__ bias, float* __restrict__ C)
{
    __shared__ float As[8 * 132];   // [k][m], pad 132
    __shared__ float Ws[8 * 132];   // [k][n]
    const int K = EE;
    const int bm = blockIdx.y * 128;
    const int bn = blockIdx.x * 128;
    const int tid = threadIdx.x;
    const int tx = tid & 15;        // n micro
    const int ty = tid >> 4;        // m micro
    const int lrow = tid >> 1;      // 0..127
    const int lk = (tid & 1) * 4;

    const float* Ap = A + (size_t)(bm + lrow) * K + lk;
    const float* Wp = W + (size_t)(bn + lrow) * K + lk;

    float acc[8][8];
#pragma unroll
    for (int i = 0; i < 8; i++)
#pragma unroll
        for (int j = 0; j < 8; j++) acc[i][j] = 0.0f;

    float4 a4 = *(const float4*)(Ap);
    float4 w4 = *(const float4*)(Wp);

    for (int k0 = 0; k0 < K; k0 += 8) {
        As[(lk + 0) * 132 + lrow] = a4.x;
        As[(lk + 1) * 132 + lrow] = a4.y;
        As[(lk + 2) * 132 + lrow] = a4.z;
        As[(lk + 3) * 132 + lrow] = a4.w;
        Ws[(lk + 0) * 132 + lrow] = w4.x;
        Ws[(lk + 1) * 132 + lrow] = w4.y;
        Ws[(lk + 2) * 132 + lrow] = w4.z;
        Ws[(lk + 3) * 132 + lrow] = w4.w;
        __syncthreads();

        if (k0 + 8 < K) {
            a4 = *(const float4*)(Ap + k0 + 8);
            w4 = *(const float4*)(Wp + k0 + 8);
        }

#pragma unroll
        for (int kk = 0; kk < 8; kk++) {
            float ar[8], wr[8];
            *(float4*)&ar[0] = *(const float4*)&As[kk * 132 + ty * 8];
            *(float4*)&ar[4] = *(const float4*)&As[kk * 132 + ty * 8 + 4];
            *(float4*)&wr[0] = *(const float4*)&Ws[kk * 132 + tx * 8];
            *(float4*)&wr[4] = *(const float4*)&Ws[kk * 132 + tx * 8 + 4];
#pragma unroll
            for (int i = 0; i < 8; i++)
#pragma unroll
                for (int j = 0; j < 8; j++)
                    acc[i][j] += ar[i] * wr[j];
        }
        __syncthreads();
    }

#pragma unroll
    for (int i = 0; i < 8; i++) {
        const int m = bm + ty * 8 + i;
        float* Cp = C + (size_t)m * EE + bn + tx * 8;
#pragma unroll
        for (int j = 0; j < 8; j++)
            Cp[j] = acc[i][j] + bias[bn + tx * 8 + j];
    }
}

// ---------------------------------------------------------------------------
// Flash attention, fp32.
// Per block: (b, h, q-tile of 128 rows). k-tile = 128.
// Smem: Qs/Ks d-major [64][128] XOR-swizzled, Vs [128][64] natural,
//       Pt = P^T [128][128] XOR-swizzled. Total 160 KB dynamic.
// S-tile computed transposed: thread (g = tid&15, w = tid>>4) owns
// k-cols g*8..g*8+7 and q-rows w*8..w*8+7, so the 16 lanes sharing w hold a
// full q-row -> width-16 shfl.xor row reductions; P^T stores are float4.
// PV: thread owns q-rows w*8..+7, d-cols g*4..+3.
// ---------------------------------------------------------------------------
__global__ __launch_bounds__(256, 1)
void attn_kernel(float* __restrict__ Out)
{
    extern __shared__ float sm[];
    float* Qs = sm;                 // 64*128
    float* Ks = Qs + 64 * 128;      // 64*128
    float* Vs = Ks + 64 * 128;      // 128*64
    float* Pt = Vs + 128 * 64;      // 128*128
    float4* Qs4 = (float4*)Qs;
    float4* Ks4 = (float4*)Ks;
    float4* Pt4 = (float4*)Pt;

    const int b = blockIdx.z;
    const int h = blockIdx.y;
    const int q0 = blockIdx.x * 128;
    const int tid = threadIdx.x;
    const int g = tid & 15;
    const int w = tid >> 4;
    const size_t base = (size_t)b * SS * EE + (size_t)h * DD;

    // Load Q tile transposed (d-major) with XOR swizzle on r-blocks.
    for (int t = tid; t < 128 * 16; t += 256) {
        const int r  = t >> 4;
        const int d4 = (t & 15) << 2;
        const float4 v = *(const float4*)(g_q + base + (size_t)(q0 + r) * EE + d4);
        const int r4 = r >> 2, rm = r & 3;
        const int sd = (d4 >> 3) & 7;     // same for d4..d4+3
        Qs[((d4 + 0) << 7) + ((r4 ^ sd) << 2) + rm] = v.x;
        Qs[((d4 + 1) << 7) + ((r4 ^ sd) << 2) + rm] = v.y;
        Qs[((d4 + 2) << 7) + ((r4 ^ sd) << 2) + rm] = v.z;
        Qs[((d4 + 3) << 7) + ((r4 ^ sd) << 2) + rm] = v.w;
    }

    float mrow[8], lrs[8], o[8][4];
#pragma unroll
    for (int j = 0; j < 8; j++) {
        mrow[j] = -1e30f;
        lrs[j] = 0.0f;
#pragma unroll
        for (int dd = 0; dd < 4; dd++) o[j][dd] = 0.0f;
    }

    for (int kt = 0; kt < SS; kt += 128) {
        __syncthreads();   // previous iteration's PV reads of Ks/Vs/Pt done

        // Load K (transposed+swizzled) and V (natural) tiles
        for (int t = tid; t < 128 * 16; t += 256) {
            const int r  = t >> 4;
            const int d4 = (t & 15) << 2;
            const size_t goff = base + (size_t)(kt + r) * EE + d4;
            const float4 kv = *(const float4*)(g_k + goff);
            const int r4 = r >> 2, rm = r & 3;
            const int sd = (d4 >> 3) & 7;
            Ks[((d4 + 0) << 7) + ((r4 ^ sd) << 2) + rm] = kv.x;
            Ks[((d4 + 1) << 7) + ((r4 ^ sd) << 2) + rm] = kv.y;
            Ks[((d4 + 2) << 7) + ((r4 ^ sd) << 2) + rm] = kv.z;
            Ks[((d4 + 3) << 7) + ((r4 ^ sd) << 2) + rm] = kv.w;
            const float4 vv = *(const float4*)(g_v + goff);
            *(float4*)&Vs[(r << 6) + d4] = vv;
        }
        __syncthreads();

        // S^T tile: acc[i][j] = sum_d K[c=g*8+i, d] * Q[r=w*8+j, d]
        float acc[8][8];
#pragma unroll
        for (int i = 0; i < 8; i++)
#pragma unroll
            for (int j = 0; j < 8; j++) acc[i][j] = 0.0f;

#pragma unroll 8
        for (int d = 0; d < 64; d++) {
            const int sd = (d >> 3) & 7;
            const float4 ka = Ks4[(d << 5) + ((g * 2) ^ sd)];
            const float4 kb = Ks4[(d << 5) + ((g * 2 + 1) ^ sd)];
            const float4 qa = Qs4[(d << 5) + ((w * 2) ^ sd)];
            const float4 qb = Qs4[(d << 5) + ((w * 2 + 1) ^ sd)];
            const float kc[8] = {ka.x, ka.y, ka.z, ka.w, kb.x, kb.y, kb.z, kb.w};
            const float qr[8] = {qa.x, qa.y, qa.z, qa.w, qb.x, qb.y, qb.z, qb.w};
#pragma unroll
            for (int i = 0; i < 8; i++)
#pragma unroll
                for (int j = 0; j < 8; j++)
                    acc[i][j] += kc[i] * qr[j];
        }

        // scores = floor(dot / 8)  (exactly matches reference: /8 is exact)
#pragma unroll
        for (int i = 0; i < 8; i++)
#pragma unroll
            for (int j = 0; j < 8; j++)
                acc[i][j] = floorf(acc[i][j] * 0.125f);

        // Row max over the 128 k-cols of each q-row (8 local + 16 lanes)
        float mt[8];
#pragma unroll
        for (int j = 0; j < 8; j++) {
            float m = acc[0][j];
#pragma unroll
            for (int i = 1; i < 8; i++) m = fmaxf(m, acc[i][j]);
            mt[j] = m;
        }
#pragma unroll
        for (int off = 8; off >= 1; off >>= 1)
#pragma unroll
            for (int j = 0; j < 8; j++)
                mt[j] = fmaxf(mt[j], __shfl_xor_sync(0xffffffffu, mt[j], off));

        float scj[8], rs[8];
#pragma unroll
        for (int j = 0; j < 8; j++) {
            const float mn = fmaxf(mrow[j], mt[j]);
            scj[j] = __expf(mrow[j] - mn);   // 0 on first tile (mrow=-1e30)
            mrow[j] = mn;
            float s = 0.0f;
#pragma unroll
            for (int i = 0; i < 8; i++) {
                acc[i][j] = __expf(acc[i][j] - mn);
                s += acc[i][j];
            }
            rs[j] = s;
        }
#pragma unroll
        for (int off = 8; off >= 1; off >>= 1)
#pragma unroll
            for (int j = 0; j < 8; j++)
                rs[j] += __shfl_xor_sync(0xffffffffu, rs[j], off);
#pragma unroll
        for (int j = 0; j < 8; j++) {
            lrs[j] = lrs[j] * scj[j] + rs[j];
#pragma unroll
            for (int dd = 0; dd < 4; dd++) o[j][dd] *= scj[j];
        }

        // Store P^T (c-major, r float4-contiguous, swizzled)
#pragma unroll
        for (int i = 0; i < 8; i++) {
            const int c = g * 8 + i;
            const int sw = g & 7;   // (c>>3)&7
            Pt4[(c << 5) + ((w * 2) ^ sw)] =
                make_float4(acc[i][0], acc[i][1], acc[i][2], acc[i][3]);
            Pt4[(c << 5) + ((w * 2 + 1) ^ sw)] =
                make_float4(acc[i][4], acc[i][5], acc[i][6], acc[i][7]);
        }
        __syncthreads();

        // O[r, d] += sum_k P[r,k] * V[k,d]; thread: rows w*8..+7, d = g*4..+3
#pragma unroll 8
        for (int k = 0; k < 128; k++) {
            const int sw = (k >> 3) & 7;
            const float4 p0 = Pt4[(k << 5) + ((w * 2) ^ sw)];
            const float4 p1 = Pt4[(k << 5) + ((w * 2 + 1) ^ sw)];
            const float4 vv = *(const float4*)&Vs[(k << 6) + (g << 2)];
            const float pr[8] = {p0.x, p0.y, p0.z, p0.w, p1.x, p1.y, p1.z, p1.w};
#pragma unroll
            for (int j = 0; j < 8; j++) {
                o[j][0] += pr[j] * vv.x;
                o[j][1] += pr[j] * vv.y;
                o[j][2] += pr[j] * vv.z;
                o[j][3] += pr[j] * vv.w;
            }
        }
    }

    // Epilogue: normalize and store. Out layout == [B, S, H*D], col h*64+g*4
#pragma unroll
    for (int j = 0; j < 8; j++) {
        const float inv = 1.0f / lrs[j];
        const int r = q0 + w * 8 + j;
        const float4 ov = make_float4(o[j][0] * inv, o[j][1] * inv,
                                      o[j][2] * inv, o[j][3] * inv);
        *(float4*)(Out + base + (size_t)r * EE + (g << 2)) = ov;
    }
}

// ---------------------------------------------------------------------------
extern "C" void kernel_launch(void* const* d_in, const int* in_sizes, int n_in,
                              void* d_out, int out_size)
{
    const float* key   = (const float*)d_in[0];
    const float* query = (const float*)d_in[1];
    const float* value = (const float*)d_in[2];
    const float* Wq    = (const float*)d_in[3];
    const float* bq    = (const float*)d_in[4];
    const float* Wk    = (const float*)d_in[5];
    const float* bk    = (const float*)d_in[6];
    const float* Wv    = (const float*)d_in[7];
    const float* bv    = (const float*)d_in[8];
    float* out = (float*)d_out;

    void *pq = 0, *pk = 0, *pv = 0;
    cudaGetSymbolAddress(&pq, g_q);
    cudaGetSymbolAddress(&pk, g_k);
    cudaGetSymbolAddress(&pv, g_v);

    const int ATTN_SMEM = (64 * 128 + 64 * 128 + 128 * 64 + 128 * 128) * 4; // 160 KB
    cudaFuncSetAttribute(attn_kernel, cudaFuncAttributeMaxDynamicSharedMemorySize,
                         ATTN_SMEM);

    dim3 pgrid(EE / 128, MM / 128);
    proj_gemm<<<pgrid, 256>>>(query, Wq, bq, (float*)pq);
    proj_gemm<<<pgrid, 256>>>(key,   Wk, bk, (float*)pk);
    proj_gemm<<<pgrid, 256>>>(value, Wv, bv, (float*)pv);

    dim3 agrid(SS / 128, HH, BB);
    attn_kernel<<<agrid, 256, ATTN_SMEM>>>(out);
}

// round 5
// speedup vs baseline: 1.0718x; 1.0718x over previous
#include <cuda_runtime.h>
#include <cuda_bf16.h>
#include <math.h>
#include <stdint.h>

#define BB 4
#define SS 2048
#define EE 1024
#define HH 16
#define DD 64
#define MM (BB*SS)

// Projected q, k, v: [B*S, E] row-major (col = h*64 + d)
__device__ float g_q[MM * EE];
__device__ float g_k[MM * EE];
__device__ float g_v[MM * EE];

// bf16 split planes: activations [tensor][plane][M*E], weights [tensor][plane][E*E]
__device__ uint16_t g_sa[3][3][MM * EE];
__device__ uint16_t g_sw[3][3][EE * EE];

// ===========================================================================
// helpers
// ===========================================================================
__device__ __forceinline__ uint32_t smem_u32(const void* p) {
    uint32_t a;
    asm("{ .reg .u64 t; cvta.to.shared.u64 t, %1; cvt.u32.u64 %0, t; }"
        : "=r"(a) : "l"(p));
    return a;
}
__device__ __forceinline__ uint32_t sw128(uint32_t off) {
    return off ^ ((off >> 3) & 0x70);
}
__device__ __forceinline__ void split3(float x, uint16_t& b0, uint16_t& b1, uint16_t& b2) {
    __nv_bfloat16 h0 = __float2bfloat16_rn(x);
    float r = x - __bfloat162float(h0);
    __nv_bfloat16 h1 = __float2bfloat16_rn(r);
    r -= __bfloat162float(h1);
    __nv_bfloat16 h2 = __float2bfloat16_rn(r);
    b0 = __bfloat16_as_ushort(h0);
    b1 = __bfloat16_as_ushort(h1);
    b2 = __bfloat16_as_ushort(h2);
}
__device__ __forceinline__ void ldsm4(uint32_t* r, uint32_t addr) {
    asm volatile("ldmatrix.sync.aligned.m8n8.x4.shared.b16 {%0,%1,%2,%3}, [%4];"
        : "=r"(r[0]), "=r"(r[1]), "=r"(r[2]), "=r"(r[3]) : "r"(addr));
}
// In-place accumulate (for the low-order correction chains)
__device__ __forceinline__ void mma16816(float* c, const uint32_t* a,
                                         uint32_t b0, uint32_t b1) {
    asm volatile("mma.sync.aligned.m16n8k16.row.col.f32.bf16.bf16.f32 "
        "{%0,%1,%2,%3}, {%4,%5,%6,%7}, {%8,%9}, {%0,%1,%2,%3};"
        : "+f"(c[0]), "+f"(c[1]), "+f"(c[2]), "+f"(c[3])
        : "r"(a[0]), "r"(a[1]), "r"(a[2]), "r"(a[3]), "r"(b0), "r"(b1));
}
// Zero-C variant: d = A*B (k16 partial sum only; no chained accumulate)
__device__ __forceinline__ void mma16816_z(float* d, const uint32_t* a,
                                           uint32_t b0, uint32_t b1) {
    asm volatile("mma.sync.aligned.m16n8k16.row.col.f32.bf16.bf16.f32 "
        "{%0,%1,%2,%3}, {%4,%5,%6,%7}, {%8,%9}, {%10,%11,%12,%13};"
        : "=f"(d[0]), "=f"(d[1]), "=f"(d[2]), "=f"(d[3])
        : "r"(a[0]), "r"(a[1]), "r"(a[2]), "r"(a[3]), "r"(b0), "r"(b1),
          "f"(0.0f), "f"(0.0f), "f"(0.0f), "f"(0.0f));
}
#define CPASYNC16(s, g) \
    asm volatile("cp.async.cg.shared.global [%0], [%1], 16;" :: "r"(s), "l"(g))
#define CP_COMMIT() asm volatile("cp.async.commit_group;" ::: "memory")
#define CP_WAIT1()  asm volatile("cp.async.wait_group 1;" ::: "memory")
#define CP_WAIT0()  asm volatile("cp.async.wait_group 0;" ::: "memory")

// ===========================================================================
// Split conversion kernels
// ===========================================================================
__global__ __launch_bounds__(256)
void split_act(const float* __restrict__ q, const float* __restrict__ k,
               const float* __restrict__ v)
{
    const int z = blockIdx.y;
    const float* src = (z == 0) ? q : (z == 1) ? k : v;
    const size_t i = ((size_t)blockIdx.x * 256 + threadIdx.x) * 4;
    const float4 x = *(const float4*)(src + i);
    uint16_t b0[4], b1[4], b2[4];
    split3(x.x, b0[0], b1[0], b2[0]);
    split3(x.y, b0[1], b1[1], b2[1]);
    split3(x.z, b0[2], b1[2], b2[2]);
    split3(x.w, b0[3], b1[3], b2[3]);
    *(ushort4*)&g_sa[z][0][i] = make_ushort4(b0[0], b0[1], b0[2], b0[3]);
    *(ushort4*)&g_sa[z][1][i] = make_ushort4(b1[0], b1[1], b1[2], b1[3]);
    *(ushort4*)&g_sa[z][2][i] = make_ushort4(b2[0], b2[1], b2[2], b2[3]);
}

__global__ __launch_bounds__(256)
void split_w(const float* __restrict__ wq, const float* __restrict__ wk,
             const float* __restrict__ wv)
{
    const int z = blockIdx.y;
    const float* src = (z == 0) ? wq : (z == 1) ? wk : wv;
    const size_t i = ((size_t)blockIdx.x * 256 + threadIdx.x) * 4;
    const float4 x = *(const float4*)(src + i);
    uint16_t b0[4], b1[4], b2[4];
    split3(x.x, b0[0], b1[0], b2[0]);
    split3(x.y, b0[1], b1[1], b2[1]);
    split3(x.z, b0[2], b1[2], b2[2]);
    split3(x.w, b0[3], b1[3], b2[3]);
    *(ushort4*)&g_sw[z][0][i] = make_ushort4(b0[0], b0[1], b0[2], b0[3]);
    *(ushort4*)&g_sw[z][1][i] = make_ushort4(b1[0], b1[1], b1[2], b1[3]);
    *(ushort4*)&g_sw[z][2][i] = make_ushort4(b2[0], b2[1], b2[2], b2[3]);
}

// ===========================================================================
// Projection GEMM via mma.sync bf16x6 (fp32 emulation, precision-structured).
// Main chain (plane0 x plane0): every HMMA issued with C=0, k16 partials
// drained into accH by fp32 RN FADDs (64-add chain per output — shorter than
// a scalar K=1024 loop). Correction chains accumulate in accL (magnitude
// ~2^-9, so 2^-21 addends keep 14 bits). C = accH + accL + bias.
// ===========================================================================
#define TILE_B   16384          // 128 rows x 128 bytes (one bf16 plane tile)
#define STAGE_B  (6 * TILE_B)   // 96 KB
#define PROJ_SMEM (2 * STAGE_B) // 192 KB
#define KT_STEPS 16

__global__ __launch_bounds__(256, 1)
void proj_mma(const float* __restrict__ bq, const float* __restrict__ bk,
              const float* __restrict__ bv,
              float* __restrict__ Cq, float* __restrict__ Ck,
              float* __restrict__ Cv)
{
    extern __shared__ char smem[];
    const uint32_t sb = smem_u32(smem);
    const int tid = threadIdx.x;
    const int wid = tid >> 5;
    const int l   = tid & 31;
    const int wm = wid >> 2;
    const int wn = wid & 3;

    const int z  = blockIdx.z;
    const int bn = blockIdx.x * 128;
    const int bm = blockIdx.y * 128;
    const float* bias = (z == 0) ? bq : (z == 1) ? bk : bv;
    float*       C    = (z == 0) ? Cq : (z == 1) ? Ck : Cv;

    // Precomputed swizzled ldmatrix lane offsets (relative to tile base).
    uint32_t swA[4], swB[2];
#pragma unroll
    for (int mi = 0; mi < 4; mi++)
        swA[mi] = sw128((uint32_t)((wm * 64 + mi * 16 + (l & 15)) * 128
                                   + ((l >> 4) << 4)));
#pragma unroll
    for (int nh = 0; nh < 2; nh++)
        swB[nh] = sw128((uint32_t)((wn * 32 + nh * 16 + ((l >> 4) & 1) * 8
                                    + (l & 7)) * 128 + (((l >> 3) & 1) << 4)));

    float accH[4][4][4];   // main-plane sum, fp32 FADD accumulation
    float accL[4][4][4];   // low-order correction sum, mma accumulation
#pragma unroll
    for (int mi = 0; mi < 4; mi++)
#pragma unroll
        for (int ni = 0; ni < 4; ni++)
#pragma unroll
            for (int c = 0; c < 4; c++) {
                accH[mi][ni][c] = 0.0f;
                accL[mi][ni][c] = 0.0f;
            }

    auto load_stage = [&](int kt, int st) {
        const uint32_t stage = sb + st * STAGE_B;
#pragma unroll
        for (int i = 0; i < 24; i++) {
            const int idx = tid + i * 256;
            const int plane = idx >> 10;
            const int chunk = idx & 1023;
            const int r = chunk >> 3;
            const int c = chunk & 7;
            const uint16_t* gp = (plane < 3)
                ? &g_sa[z][plane][(size_t)(bm + r) * EE + kt * 64 + c * 8]
                : &g_sw[z][plane - 3][(size_t)(bn + r) * EE + kt * 64 + c * 8];
            const uint32_t s = stage + plane * TILE_B + sw128((uint32_t)(r * 128 + c * 16));
            CPASYNC16(s, gp);
        }
        CP_COMMIT();
    };

    load_stage(0, 0);

    // correction chains: (a-plane, w-plane)
    const int pa[5] = {1, 0, 2, 1, 0};
    const int pb[5] = {0, 1, 0, 1, 2};

    for (int kt = 0; kt < KT_STEPS; kt++) {
        if (kt + 1 < KT_STEPS) {
            load_stage(kt + 1, (kt + 1) & 1);
            CP_WAIT1();
        } else {
            CP_WAIT0();
        }
        __syncthreads();

        const uint32_t As = sb + (kt & 1) * STAGE_B;
        const uint32_t Bs = As + 3 * TILE_B;

        // ---- main chain (0,0): C=0 HMMA + fp32 drain ----
#pragma unroll
        for (int ks = 0; ks < 4; ks++) {
            const uint32_t kx = (uint32_t)(ks << 5);
            uint32_t a[4][4], b[2][4];
#pragma unroll
            for (int mi = 0; mi < 4; mi++)
                ldsm4(a[mi], As + (swA[mi] ^ kx));
#pragma unroll
            for (int nh = 0; nh < 2; nh++)
                ldsm4(b[nh], Bs + (swB[nh] ^ kx));
#pragma unroll
            for (int mi = 0; mi < 4; mi++) {
#pragma unroll
                for (int ni = 0; ni < 4; ni++) {
                    float t[4];
                    const uint32_t bb0 = b[ni >> 1][(ni & 1) * 2];
                    const uint32_t bb1 = b[ni >> 1][(ni & 1) * 2 + 1];
                    mma16816_z(t, a[mi], bb0, bb1);
                    accH[mi][ni][0] += t[0];
                    accH[mi][ni][1] += t[1];
                    accH[mi][ni][2] += t[2];
                    accH[mi][ni][3] += t[3];
                }
            }
        }

        // ---- correction chains into accL (chained mma accumulate) ----
#pragma unroll
        for (int p = 0; p < 5; p++) {
            const uint32_t at = As + pa[p] * TILE_B;
            const uint32_t bt = Bs + pb[p] * TILE_B;
#pragma unroll
            for (int ks = 0; ks < 4; ks++) {
                const uint32_t kx = (uint32_t)(ks << 5);
                uint32_t a[4][4], b[2][4];
#pragma unroll
                for (int mi = 0; mi < 4; mi++)
                    ldsm4(a[mi], at + (swA[mi] ^ kx));
#pragma unroll
                for (int nh = 0; nh < 2; nh++)
                    ldsm4(b[nh], bt + (swB[nh] ^ kx));
#pragma unroll
                for (int mi = 0; mi < 4; mi++) {
                    mma16816(accL[mi][0], a[mi], b[0][0], b[0][1]);
                    mma16816(accL[mi][1], a[mi], b[0][2], b[0][3]);
                    mma16816(accL[mi][2], a[mi], b[1][0], b[1][1]);
                    mma16816(accL[mi][3], a[mi], b[1][2], b[1][3]);
                }
            }
        }
        __syncthreads();   // stage may be overwritten next iteration
    }

    // Epilogue: c0=C[r][c], c1=C[r][c+1], c2=C[r+8][c], c3=C[r+8][c+1]
#pragma unroll
    for (int mi = 0; mi < 4; mi++) {
        const int r0 = bm + wm * 64 + mi * 16 + (l >> 2);
#pragma unroll
        for (int ni = 0; ni < 4; ni++) {
            const int cb = bn + wn * 32 + ni * 8 + 2 * (l & 3);
            const float bx = bias[cb], by = bias[cb + 1];
            float2 v0 = make_float2(accH[mi][ni][0] + accL[mi][ni][0] + bx,
                                    accH[mi][ni][1] + accL[mi][ni][1] + by);
            float2 v1 = make_float2(accH[mi][ni][2] + accL[mi][ni][2] + bx,
                                    accH[mi][ni][3] + accL[mi][ni][3] + by);
            *(float2*)(C + (size_t)r0 * EE + cb) = v0;
            *(float2*)(C + (size_t)(r0 + 8) * EE + cb) = v1;
        }
    }
}

// ---------------------------------------------------------------------------
// Flash attention, fp32 scalar (unchanged — at FFMA roofline).
// ---------------------------------------------------------------------------
__global__ __launch_bounds__(256, 1)
void attn_kernel(float* __restrict__ Out)
{
    extern __shared__ float sm[];
    float* Qs = sm;                 // 64*128
    float* Ks = Qs + 64 * 128;      // 64*128
    float* Vs = Ks + 64 * 128;      // 128*64
    float* Pt = Vs + 128 * 64;      // 128*128
    float4* Qs4 = (float4*)Qs;
    float4* Ks4 = (float4*)Ks;
    float4* Pt4 = (float4*)Pt;

    const int b = blockIdx.z;
    const int h = blockIdx.y;
    const int q0 = blockIdx.x * 128;
    const int tid = threadIdx.x;
    const int g = tid & 15;
    const int w = tid >> 4;
    const size_t base = (size_t)b * SS * EE + (size_t)h * DD;

    for (int t = tid; t < 128 * 16; t += 256) {
        const int r  = t >> 4;
        const int d4 = (t & 15) << 2;
        const float4 v = *(const float4*)(g_q + base + (size_t)(q0 + r) * EE + d4);
        const int r4 = r >> 2, rm = r & 3;
        const int sd = (d4 >> 3) & 7;
        Qs[((d4 + 0) << 7) + ((r4 ^ sd) << 2) + rm] = v.x;
        Qs[((d4 + 1) << 7) + ((r4 ^ sd) << 2) + rm] = v.y;
        Qs[((d4 + 2) << 7) + ((r4 ^ sd) << 2) + rm] = v.z;
        Qs[((d4 + 3) << 7) + ((r4 ^ sd) << 2) + rm] = v.w;
    }

    float mrow[8], lrs[8], o[8][4];
#pragma unroll
    for (int j = 0; j < 8; j++) {
        mrow[j] = -1e30f;
        lrs[j] = 0.0f;
#pragma unroll
        for (int dd = 0; dd < 4; dd++) o[j][dd] = 0.0f;
    }

    for (int kt = 0; kt < SS; kt += 128) {
        __syncthreads();

        for (int t = tid; t < 128 * 16; t += 256) {
            const int r  = t >> 4;
            const int d4 = (t & 15) << 2;
            const size_t goff = base + (size_t)(kt + r) * EE + d4;
            const float4 kv = *(const float4*)(g_k + goff);
            const int r4 = r >> 2, rm = r & 3;
            const int sd = (d4 >> 3) & 7;
            Ks[((d4 + 0) << 7) + ((r4 ^ sd) << 2) + rm] = kv.x;
            Ks[((d4 + 1) << 7) + ((r4 ^ sd) << 2) + rm] = kv.y;
            Ks[((d4 + 2) << 7) + ((r4 ^ sd) << 2) + rm] = kv.z;
            Ks[((d4 + 3) << 7) + ((r4 ^ sd) << 2) + rm] = kv.w;
            const float4 vv = *(const float4*)(g_v + goff);
            *(float4*)&Vs[(r << 6) + d4] = vv;
        }
        __syncthreads();

        float acc[8][8];
#pragma unroll
        for (int i = 0; i < 8; i++)
#pragma unroll
            for (int j = 0; j < 8; j++) acc[i][j] = 0.0f;

#pragma unroll 8
        for (int d = 0; d < 64; d++) {
            const int sd = (d >> 3) & 7;
            const float4 ka = Ks4[(d << 5) + ((g * 2) ^ sd)];
            const float4 kb = Ks4[(d << 5) + ((g * 2 + 1) ^ sd)];
            const float4 qa = Qs4[(d << 5) + ((w * 2) ^ sd)];
            const float4 qb = Qs4[(d << 5) + ((w * 2 + 1) ^ sd)];
            const float kc[8] = {ka.x, ka.y, ka.z, ka.w, kb.x, kb.y, kb.z, kb.w};
            const float qr[8] = {qa.x, qa.y, qa.z, qa.w, qb.x, qb.y, qb.z, qb.w};
#pragma unroll
            for (int i = 0; i < 8; i++)
#pragma unroll
                for (int j = 0; j < 8; j++)
                    acc[i][j] += kc[i] * qr[j];
        }

#pragma unroll
        for (int i = 0; i < 8; i++)
#pragma unroll
            for (int j = 0; j < 8; j++)
                acc[i][j] = floorf(acc[i][j] * 0.125f);

        float mt[8];
#pragma unroll
        for (int j = 0; j < 8; j++) {
            float m = acc[0][j];
#pragma unroll
            for (int i = 1; i < 8; i++) m = fmaxf(m, acc[i][j]);
            mt[j] = m;
        }
#pragma unroll
        for (int off = 8; off >= 1; off >>= 1)
#pragma unroll
            for (int j = 0; j < 8; j++)
                mt[j] = fmaxf(mt[j], __shfl_xor_sync(0xffffffffu, mt[j], off));

        float scj[8], rs[8];
#pragma unroll
        for (int j = 0; j < 8; j++) {
            const float mn = fmaxf(mrow[j], mt[j]);
            scj[j] = __expf(mrow[j] - mn);
            mrow[j] = mn;
            float s = 0.0f;
#pragma unroll
            for (int i = 0; i < 8; i++) {
                acc[i][j] = __expf(acc[i][j] - mn);
                s += acc[i][j];
            }
            rs[j] = s;
        }
#pragma unroll
        for (int off = 8; off >= 1; off >>= 1)
#pragma unroll
            for (int j = 0; j < 8; j++)
                rs[j] += __shfl_xor_sync(0xffffffffu, rs[j], off);
#pragma unroll
        for (int j = 0; j < 8; j++) {
            lrs[j] = lrs[j] * scj[j] + rs[j];
#pragma unroll
            for (int dd = 0; dd < 4; dd++) o[j][dd] *= scj[j];
        }

#pragma unroll
        for (int i = 0; i < 8; i++) {
            const int c = g * 8 + i;
            const int sw = g & 7;
            Pt4[(c << 5) + ((w * 2) ^ sw)] =
                make_float4(acc[i][0], acc[i][1], acc[i][2], acc[i][3]);
            Pt4[(c << 5) + ((w * 2 + 1) ^ sw)] =
                make_float4(acc[i][4], acc[i][5], acc[i][6], acc[i][7]);
        }
        __syncthreads();

#pragma unroll 8
        for (int k = 0; k < 128; k++) {
            const int sw = (k >> 3) & 7;
            const float4 p0 = Pt4[(k << 5) + ((w * 2) ^ sw)];
            const float4 p1 = Pt4[(k << 5) + ((w * 2 + 1) ^ sw)];
            const float4 vv = *(const float4*)&Vs[(k << 6) + (g << 2)];
            const float pr[8] = {p0.x, p0.y, p0.z, p0.w, p1.x, p1.y, p1.z, p1.w};
#pragma unroll
            for (int j = 0; j < 8; j++) {
                o[j][0] += pr[j] * vv.x;
                o[j][1] += pr[j] * vv.y;
                o[j][2] += pr[j] * vv.z;
                o[j][3] += pr[j] * vv.w;
            }
        }
    }

#pragma unroll
    for (int j = 0; j < 8; j++) {
        const float inv = 1.0f / lrs[j];
        const int r = q0 + w * 8 + j;
        const float4 ov = make_float4(o[j][0] * inv, o[j][1] * inv,
                                      o[j][2] * inv, o[j][3] * inv);
        *(float4*)(Out + base + (size_t)r * EE + (g << 2)) = ov;
    }
}

// ---------------------------------------------------------------------------
extern "C" void kernel_launch(void* const* d_in, const int* in_sizes, int n_in,
                              void* d_out, int out_size)
{
    const float* key   = (const float*)d_in[0];
    const float* query = (const float*)d_in[1];
    const float* value = (const float*)d_in[2];
    const float* Wq    = (const float*)d_in[3];
    const float* bq    = (const float*)d_in[4];
    const float* Wk    = (const float*)d_in[5];
    const float* bk    = (const float*)d_in[6];
    const float* Wv    = (const float*)d_in[7];
    const float* bv    = (const float*)d_in[8];
    float* out = (float*)d_out;

    void *pq = 0, *pk = 0, *pv = 0;
    cudaGetSymbolAddress(&pq, g_q);
    cudaGetSymbolAddress(&pk, g_k);
    cudaGetSymbolAddress(&pv, g_v);

    cudaFuncSetAttribute(proj_mma, cudaFuncAttributeMaxDynamicSharedMemorySize,
                         PROJ_SMEM);
    const int ATTN_SMEM = (64 * 128 + 64 * 128 + 128 * 64 + 128 * 128) * 4;
    cudaFuncSetAttribute(attn_kernel, cudaFuncAttributeMaxDynamicSharedMemorySize,
                         ATTN_SMEM);

    // bf16x3 split planes (once per launch; deterministic)
    dim3 sgrid(MM * EE / 1024, 3);
    split_act<<<sgrid, 256>>>(query, key, value);
    dim3 wgrid(EE * EE / 1024, 3);
    split_w<<<wgrid, 256>>>(Wq, Wk, Wv);

    dim3 pgrid(EE / 128, MM / 128, 3);
    proj_mma<<<pgrid, 256, PROJ_SMEM>>>(bq, bk, bv,
                                        (float*)pq, (float*)pk, (float*)pv);

    dim3 agrid(SS / 128, HH, BB);
    attn_kernel<<<agrid, 256, ATTN_SMEM>>>(out);
}